// round 1
// baseline (speedup 1.0000x reference)
#include <cuda_runtime.h>

#define N_NODES  50000
#define N_EDGES  800000
#define N_GRAPHS 128
#define HID      64
#define LAYERS   3

// Scratch (allocation-free rule: __device__ globals).
// g_agg invariant: zero at entry to every kernel_launch call. It is zero at
// module load, and mlp_kernel re-zeros each row it consumes, so the invariant
// holds across graph replays deterministically.
__device__ float g_h[N_NODES * HID];
__device__ float g_agg[N_NODES * HID];

// ---------------------------------------------------------------------------
// h[n] = emb[feats[n]]   (one thread per float4)
// ---------------------------------------------------------------------------
__global__ void embed_kernel(const int* __restrict__ feats,
                             const float* __restrict__ emb) {
    int i = blockIdx.x * blockDim.x + threadIdx.x;
    if (i >= N_NODES * (HID / 4)) return;
    int n = i >> 4;
    int c = i & 15;
    int f = __ldg(feats + n);
    float4 v = ((const float4*)emb)[f * (HID / 4) + c];
    ((float4*)g_h)[i] = v;
}

// ---------------------------------------------------------------------------
// agg[dst[e]] += h[src[e]]   (16 threads per edge, one float4 each,
// vectorized red.global.add.v4.f32 -> 4x fewer atomic ops)
// ---------------------------------------------------------------------------
__global__ void edge_kernel(const int* __restrict__ src,
                            const int* __restrict__ dst) {
    unsigned int i = blockIdx.x * blockDim.x + threadIdx.x;
    if (i >= (unsigned int)N_EDGES * 16u) return;
    int e = i >> 4;
    int c = i & 15;
    int s = __ldg(src + e);
    int d = __ldg(dst + e);
    float4 v = ((const float4*)g_h)[s * (HID / 4) + c];
    float* p = g_agg + d * HID + c * 4;
    asm volatile("red.global.add.v4.f32 [%0], {%1,%2,%3,%4};"
                 :: "l"(p), "f"(v.x), "f"(v.y), "f"(v.z), "f"(v.w)
                 : "memory");
}

// ---------------------------------------------------------------------------
// Per node: z = h + agg;  y = relu(z@W1+b1);  h = y@W2+b2.
// One thread per node; W1/W2 in smem (broadcast LDS.128 feeds 4 FMAs).
// Also re-zeros agg for the next layer / next call.
// ---------------------------------------------------------------------------
__global__ void __launch_bounds__(128)
mlp_kernel(const float* __restrict__ W1, const float* __restrict__ b1,
           const float* __restrict__ W2, const float* __restrict__ b2,
           int layer) {
    __shared__ __align__(16) float sW1[HID * HID];
    __shared__ __align__(16) float sW2[HID * HID];
    __shared__ __align__(16) float sb1[HID];
    __shared__ __align__(16) float sb2[HID];

    const float* w1 = W1 + layer * HID * HID;
    const float* w2 = W2 + layer * HID * HID;
    for (int i = threadIdx.x; i < HID * HID; i += blockDim.x) {
        sW1[i] = w1[i];
        sW2[i] = w2[i];
    }
    if (threadIdx.x < HID) {
        sb1[threadIdx.x] = b1[layer * HID + threadIdx.x];
        sb2[threadIdx.x] = b2[layer * HID + threadIdx.x];
    }
    __syncthreads();

    int n = blockIdx.x * blockDim.x + threadIdx.x;
    if (n >= N_NODES) return;

    float4* hrow = ((float4*)g_h) + n * (HID / 4);
    float4* arow = ((float4*)g_agg) + n * (HID / 4);

    float z[HID];
#pragma unroll
    for (int c = 0; c < HID / 4; c++) {
        float4 a = hrow[c];
        float4 b = arow[c];
        z[4 * c + 0] = a.x + b.x;
        z[4 * c + 1] = a.y + b.y;
        z[4 * c + 2] = a.z + b.z;
        z[4 * c + 3] = a.w + b.w;
        arow[c] = make_float4(0.f, 0.f, 0.f, 0.f);  // re-zero agg
    }

    float y[HID];
    for (int j = 0; j < HID; j += 4) {
        float4 acc = *(const float4*)&sb1[j];
#pragma unroll
        for (int k = 0; k < HID; k++) {
            float4 w = *(const float4*)&sW1[k * HID + j];
            acc.x = fmaf(z[k], w.x, acc.x);
            acc.y = fmaf(z[k], w.y, acc.y);
            acc.z = fmaf(z[k], w.z, acc.z);
            acc.w = fmaf(z[k], w.w, acc.w);
        }
        y[j + 0] = fmaxf(acc.x, 0.f);
        y[j + 1] = fmaxf(acc.y, 0.f);
        y[j + 2] = fmaxf(acc.z, 0.f);
        y[j + 3] = fmaxf(acc.w, 0.f);
    }

    for (int j = 0; j < HID; j += 4) {
        float4 acc = *(const float4*)&sb2[j];
#pragma unroll
        for (int k = 0; k < HID; k++) {
            float4 w = *(const float4*)&sW2[k * HID + j];
            acc.x = fmaf(y[k], w.x, acc.x);
            acc.y = fmaf(y[k], w.y, acc.y);
            acc.z = fmaf(y[k], w.z, acc.z);
            acc.w = fmaf(y[k], w.w, acc.w);
        }
        hrow[j >> 2] = acc;
    }
}

// ---------------------------------------------------------------------------
// out[g] = sum_{n in g} dot(h[n], Wr)   (fused pool + head)
// ---------------------------------------------------------------------------
__global__ void zero_out_kernel(float* out) {
    if (threadIdx.x < N_GRAPHS) out[threadIdx.x] = 0.f;
}

__global__ void pool_kernel(const int* __restrict__ gids,
                            const float* __restrict__ Wr,
                            float* __restrict__ out) {
    __shared__ float sWr[HID];
    if (threadIdx.x < HID) sWr[threadIdx.x] = Wr[threadIdx.x];
    __syncthreads();
    int n = blockIdx.x * blockDim.x + threadIdx.x;
    if (n >= N_NODES) return;
    const float4* hrow = ((const float4*)g_h) + n * (HID / 4);
    float acc = 0.f;
#pragma unroll
    for (int c = 0; c < HID / 4; c++) {
        float4 v = hrow[c];
        acc += v.x * sWr[4 * c + 0] + v.y * sWr[4 * c + 1]
             + v.z * sWr[4 * c + 2] + v.w * sWr[4 * c + 3];
    }
    atomicAdd(out + __ldg(gids + n), acc);
}

// ---------------------------------------------------------------------------
extern "C" void kernel_launch(void* const* d_in, const int* in_sizes, int n_in,
                              void* d_out, int out_size) {
    const int*   feats = (const int*)d_in[0];
    const int*   src   = (const int*)d_in[1];
    const int*   dst   = (const int*)d_in[2];
    const int*   gids  = (const int*)d_in[3];
    const float* emb   = (const float*)d_in[4];
    const float* W1    = (const float*)d_in[5];
    const float* b1    = (const float*)d_in[6];
    const float* W2    = (const float*)d_in[7];
    const float* b2    = (const float*)d_in[8];
    const float* Wr    = (const float*)d_in[9];
    float* out = (float*)d_out;

    embed_kernel<<<(N_NODES * 16 + 255) / 256, 256>>>(feats, emb);

    for (int l = 0; l < LAYERS; l++) {
        edge_kernel<<<(N_EDGES * 16 + 255) / 256, 256>>>(src, dst);
        mlp_kernel<<<(N_NODES + 127) / 128, 128>>>(W1, b1, W2, b2, l);
    }

    zero_out_kernel<<<1, 128>>>(out);
    pool_kernel<<<(N_NODES + 127) / 128, 128>>>(gids, Wr, out);
}

// round 2
// speedup vs baseline: 1.2165x; 1.2165x over previous
#include <cuda_runtime.h>

#define N_NODES  50000
#define N_EDGES  800000
#define N_GRAPHS 128
#define HID      64
#define LAYERS   3

// Scratch (__device__ globals — allocation-free rule).
__device__ float g_h_a[N_NODES * HID];
__device__ float g_h_b[N_NODES * HID];
__device__ int   g_deg[N_NODES];
__device__ int   g_rowptr[N_NODES + 1];
__device__ int   g_pos[N_NODES];
__device__ int   g_csr_src[N_EDGES];

// ---------------------------------------------------------------------------
// CSR build (rebuilt every call: deterministic, graph-capturable)
// ---------------------------------------------------------------------------
__global__ void zero_deg_kernel() {
    int i = blockIdx.x * blockDim.x + threadIdx.x;
    if (i < N_NODES) g_deg[i] = 0;
}

__global__ void hist_kernel(const int* __restrict__ dst) {
    int e = blockIdx.x * blockDim.x + threadIdx.x;
    if (e < N_EDGES) atomicAdd(&g_deg[__ldg(dst + e)], 1);
}

// Single-block scan over 50000 degrees -> rowptr (exclusive) + pos copy.
__global__ void __launch_bounds__(1024) scan_kernel() {
    __shared__ int ssum[1024];
    const int CH = (N_NODES + 1023) / 1024;  // 49
    int t = threadIdx.x;
    int beg = t * CH;
    int end = beg + CH; if (end > N_NODES) end = N_NODES;
    int s = 0;
    for (int i = beg; i < end; i++) s += g_deg[i];
    ssum[t] = s;
    __syncthreads();
    // Hillis-Steele inclusive scan
    for (int off = 1; off < 1024; off <<= 1) {
        int v = (t >= off) ? ssum[t - off] : 0;
        __syncthreads();
        ssum[t] += v;
        __syncthreads();
    }
    int run = ssum[t] - s;  // exclusive prefix of this chunk
    for (int i = beg; i < end; i++) {
        g_rowptr[i] = run;
        g_pos[i]    = run;
        run += g_deg[i];
    }
    if (t == 0) g_rowptr[N_NODES] = N_EDGES;
}

__global__ void scatter_kernel(const int* __restrict__ src,
                               const int* __restrict__ dst) {
    int e = blockIdx.x * blockDim.x + threadIdx.x;
    if (e >= N_EDGES) return;
    int p = atomicAdd(&g_pos[__ldg(dst + e)], 1);
    g_csr_src[p] = __ldg(src + e);
}

// ---------------------------------------------------------------------------
// h[n] = emb[feats[n]]   (one thread per float4) -> g_h_a
// ---------------------------------------------------------------------------
__global__ void embed_kernel(const int* __restrict__ feats,
                             const float* __restrict__ emb) {
    int i = blockIdx.x * blockDim.x + threadIdx.x;
    if (i >= N_NODES * (HID / 4)) return;
    int n = i >> 4;
    int c = i & 15;
    int f = __ldg(feats + n);
    ((float4*)g_h_a)[i] = ((const float4*)emb)[f * (HID / 4) + c];
}

// ---------------------------------------------------------------------------
// Fused GIN layer: z = h[n] + sum_{s in N(n)} h[s];
//                  y = relu(z@W1+b1); hout = y@W2+b2.
// 16 threads per node (each owns one float4 column), 32 nodes per 512-thread
// block. z/y in smem (broadcast LDS), weights staged in smem.
// Double-buffered h: layer parity selects in/out.
// ---------------------------------------------------------------------------
#define NPB 32  // nodes per block

__global__ void __launch_bounds__(512)
layer_kernel(const float* __restrict__ W1, const float* __restrict__ b1,
             const float* __restrict__ W2, const float* __restrict__ b2,
             int layer) {
    __shared__ __align__(16) float sW1[HID * HID];
    __shared__ __align__(16) float sW2[HID * HID];
    __shared__ __align__(16) float sb1[HID];
    __shared__ __align__(16) float sb2[HID];
    __shared__ __align__(16) float sz[NPB][HID];
    __shared__ __align__(16) float sy[NPB][HID];

    const float* hin  = (layer & 1) ? g_h_b : g_h_a;
    float*       hout = (layer & 1) ? g_h_a : g_h_b;

    const float* w1 = W1 + layer * HID * HID;
    const float* w2 = W2 + layer * HID * HID;
    for (int i = threadIdx.x; i < HID * HID; i += 512) {
        sW1[i] = w1[i];
        sW2[i] = w2[i];
    }
    if (threadIdx.x < HID) {
        sb1[threadIdx.x] = b1[layer * HID + threadIdx.x];
        sb2[threadIdx.x] = b2[layer * HID + threadIdx.x];
    }
    __syncthreads();

    const int local = threadIdx.x >> 4;   // node slot 0..31
    const int c     = threadIdx.x & 15;   // float4 column 0..15
    const int n     = blockIdx.x * NPB + local;
    const bool valid = (n < N_NODES);

    const float4* h4in = (const float4*)hin;

    // ---- aggregation (gather) ----
    float4 acc = make_float4(0.f, 0.f, 0.f, 0.f);
    if (valid) {
        acc = h4in[n * 16 + c];
        int beg = __ldg(&g_rowptr[n]);
        int end = __ldg(&g_rowptr[n + 1]);
        for (int e = beg; e < end; e++) {
            int s = __ldg(&g_csr_src[e]);
            float4 v = h4in[s * 16 + c];
            acc.x += v.x; acc.y += v.y; acc.z += v.z; acc.w += v.w;
        }
    }
    ((float4*)sz[local])[c] = acc;
    __syncwarp();

    // ---- GEMV 1: y = relu(z @ W1 + b1), this thread owns cols 4c..4c+3 ----
    {
        float4 o = *(const float4*)&sb1[4 * c];
#pragma unroll
        for (int k = 0; k < HID; k++) {
            float zk = sz[local][k];
            float4 w = *(const float4*)&sW1[k * HID + 4 * c];
            o.x = fmaf(zk, w.x, o.x);
            o.y = fmaf(zk, w.y, o.y);
            o.z = fmaf(zk, w.z, o.z);
            o.w = fmaf(zk, w.w, o.w);
        }
        o.x = fmaxf(o.x, 0.f); o.y = fmaxf(o.y, 0.f);
        o.z = fmaxf(o.z, 0.f); o.w = fmaxf(o.w, 0.f);
        ((float4*)sy[local])[c] = o;
    }
    __syncwarp();

    // ---- GEMV 2: hout = y @ W2 + b2 ----
    {
        float4 o = *(const float4*)&sb2[4 * c];
#pragma unroll
        for (int k = 0; k < HID; k++) {
            float yk = sy[local][k];
            float4 w = *(const float4*)&sW2[k * HID + 4 * c];
            o.x = fmaf(yk, w.x, o.x);
            o.y = fmaf(yk, w.y, o.y);
            o.z = fmaf(yk, w.z, o.z);
            o.w = fmaf(yk, w.w, o.w);
        }
        if (valid) ((float4*)hout)[n * 16 + c] = o;
    }
}

// ---------------------------------------------------------------------------
// out[g] = sum_{n in g} dot(h[n], Wr)  with warp-aggregated atomics
// (reads g_h_b: final layer output after 3 layers A->B->A->B)
// ---------------------------------------------------------------------------
__global__ void zero_out_kernel(float* out) {
    if (threadIdx.x < N_GRAPHS) out[threadIdx.x] = 0.f;
}

__global__ void pool_kernel(const int* __restrict__ gids,
                            const float* __restrict__ Wr,
                            float* __restrict__ out) {
    __shared__ float sWr[HID];
    if (threadIdx.x < HID) sWr[threadIdx.x] = Wr[threadIdx.x];
    __syncthreads();
    int n = blockIdx.x * blockDim.x + threadIdx.x;
    bool valid = (n < N_NODES);
    int nn = valid ? n : (N_NODES - 1);
    int g = __ldg(gids + nn);

    float acc = 0.f;
    if (valid) {
        const float4* hrow = ((const float4*)g_h_b) + n * (HID / 4);
#pragma unroll
        for (int c = 0; c < HID / 4; c++) {
            float4 v = hrow[c];
            acc += v.x * sWr[4 * c + 0] + v.y * sWr[4 * c + 1]
                 + v.z * sWr[4 * c + 2] + v.w * sWr[4 * c + 3];
        }
    }
    // graph_ids sorted -> warps are usually uniform: one atomic per warp
    int g0 = __shfl_sync(0xffffffffu, g, 0);
    bool uniform = __all_sync(0xffffffffu, g == g0);
    if (uniform) {
#pragma unroll
        for (int off = 16; off > 0; off >>= 1)
            acc += __shfl_down_sync(0xffffffffu, acc, off);
        if ((threadIdx.x & 31) == 0) atomicAdd(out + g0, acc);
    } else if (valid) {
        atomicAdd(out + g, acc);
    }
}

// ---------------------------------------------------------------------------
extern "C" void kernel_launch(void* const* d_in, const int* in_sizes, int n_in,
                              void* d_out, int out_size) {
    const int*   feats = (const int*)d_in[0];
    const int*   src   = (const int*)d_in[1];
    const int*   dst   = (const int*)d_in[2];
    const int*   gids  = (const int*)d_in[3];
    const float* emb   = (const float*)d_in[4];
    const float* W1    = (const float*)d_in[5];
    const float* b1    = (const float*)d_in[6];
    const float* W2    = (const float*)d_in[7];
    const float* b2    = (const float*)d_in[8];
    const float* Wr    = (const float*)d_in[9];
    float* out = (float*)d_out;

    // CSR build
    zero_deg_kernel<<<(N_NODES + 255) / 256, 256>>>();
    hist_kernel<<<(N_EDGES + 255) / 256, 256>>>(dst);
    scan_kernel<<<1, 1024>>>();
    scatter_kernel<<<(N_EDGES + 255) / 256, 256>>>(src, dst);

    // Embedding
    embed_kernel<<<(N_NODES * 16 + 255) / 256, 256>>>(feats, emb);

    // 3 fused GIN layers (A->B->A->B)
    const int nblk = (N_NODES + NPB - 1) / NPB;
    for (int l = 0; l < LAYERS; l++)
        layer_kernel<<<nblk, 512>>>(W1, b1, W2, b2, l);

    // Pool + head
    zero_out_kernel<<<1, 128>>>(out);
    pool_kernel<<<(N_NODES + 255) / 256, 256>>>(gids, Wr, out);
}

// round 3
// speedup vs baseline: 1.2187x; 1.0018x over previous
#include <cuda_runtime.h>

#define N_NODES  50000
#define N_EDGES  800000
#define N_GRAPHS 128
#define HID      64
#define LAYERS   3
#define NPB      64   // nodes per block in layer kernel

// Scratch (__device__ globals — allocation-free rule).
__device__ float g_h_a[N_NODES * HID];
__device__ float g_h_b[N_NODES * HID];
__device__ int   g_deg[N_NODES];
__device__ int   g_rowptr[N_NODES + 1];
__device__ int   g_pos[N_NODES];
__device__ int   g_csr_src[N_EDGES];

// ---------------------------------------------------------------------------
// CSR build (rebuilt every call: deterministic, graph-capturable)
// ---------------------------------------------------------------------------
__global__ void zero_deg_kernel() {
    int i = blockIdx.x * blockDim.x + threadIdx.x;
    if (i < N_NODES) g_deg[i] = 0;
}

__global__ void hist_kernel(const int* __restrict__ dst) {
    int e = blockIdx.x * blockDim.x + threadIdx.x;
    if (e < N_EDGES) atomicAdd(&g_deg[__ldg(dst + e)], 1);
}

__global__ void __launch_bounds__(1024) scan_kernel() {
    __shared__ int ssum[1024];
    const int CH = (N_NODES + 1023) / 1024;  // 49
    int t = threadIdx.x;
    int beg = t * CH;
    int end = beg + CH; if (end > N_NODES) end = N_NODES;
    int s = 0;
    for (int i = beg; i < end; i++) s += g_deg[i];
    ssum[t] = s;
    __syncthreads();
    for (int off = 1; off < 1024; off <<= 1) {
        int v = (t >= off) ? ssum[t - off] : 0;
        __syncthreads();
        ssum[t] += v;
        __syncthreads();
    }
    int run = ssum[t] - s;
    for (int i = beg; i < end; i++) {
        g_rowptr[i] = run;
        g_pos[i]    = run;
        run += g_deg[i];
    }
    if (t == 0) g_rowptr[N_NODES] = N_EDGES;
}

__global__ void scatter_kernel(const int* __restrict__ src,
                               const int* __restrict__ dst) {
    int e = blockIdx.x * blockDim.x + threadIdx.x;
    if (e >= N_EDGES) return;
    int p = atomicAdd(&g_pos[__ldg(dst + e)], 1);
    g_csr_src[p] = __ldg(src + e);
}

// ---------------------------------------------------------------------------
// h[n] = emb[feats[n]]
// ---------------------------------------------------------------------------
__global__ void embed_kernel(const int* __restrict__ feats,
                             const float* __restrict__ emb) {
    int i = blockIdx.x * blockDim.x + threadIdx.x;
    if (i >= N_NODES * (HID / 4)) return;
    int n = i >> 4;
    int c = i & 15;
    int f = __ldg(feats + n);
    ((float4*)g_h_a)[i] = ((const float4*)emb)[f * (HID / 4) + c];
}

// ---------------------------------------------------------------------------
// Fused GIN layer.
// Shared layout (floats, dynamic smem):
//   sW1 : [64][68]       off 0
//   sW2 : [64][68]       off 4352
//   sb1 : [64]           off 8704
//   sb2 : [64]           off 8768
//   z2  : [64][132]      off 8832   (transposed, DUPLICATED: z2[k][2n]=z2[k][2n+1])
// total 17280 floats = 69120 B dynamic smem.
// 256 threads: GEMV mapping jg=tid&15 (4 cols), ig=tid>>4 (4 nodes).
// Inner loop: 3x LDS + 8x fma.rn.f32x2 per k (16 FMAs).
// ---------------------------------------------------------------------------
#define OFF_W1 0
#define OFF_W2 4352
#define OFF_B1 8704
#define OFF_B2 8768
#define OFF_Z  8832
#define WPAD   68
#define ZPAD   132
#define SMEM_BYTES (17280 * 4)

__device__ __forceinline__ unsigned su32(const void* p) {
    return (unsigned)__cvta_generic_to_shared(p);
}

#define FMA2(d, a, b) asm("fma.rn.f32x2 %0, %1, %2, %0;" : "+l"(d) : "l"(a), "l"(b))

__global__ void __launch_bounds__(256)
layer_kernel(const float* __restrict__ W1, const float* __restrict__ b1,
             const float* __restrict__ W2, const float* __restrict__ b2,
             int layer) {
    extern __shared__ __align__(16) float sm[];

    const float* hin  = (layer & 1) ? g_h_b : g_h_a;
    float*       hout = (layer & 1) ? g_h_a : g_h_b;

    const int tid = threadIdx.x;

    // ---- stage weights/biases (padded rows) ----
    {
        const float4* w1 = (const float4*)(W1 + layer * HID * HID);
        const float4* w2 = (const float4*)(W2 + layer * HID * HID);
        for (int idx = tid; idx < 1024; idx += 256) {
            int r = idx >> 4, c = idx & 15;
            *(float4*)&sm[OFF_W1 + r * WPAD + c * 4] = w1[idx];
            *(float4*)&sm[OFF_W2 + r * WPAD + c * 4] = w2[idx];
        }
        if (tid < HID) {
            sm[OFF_B1 + tid] = b1[layer * HID + tid];
            sm[OFF_B2 + tid] = b2[layer * HID + tid];
        }
    }

    const unsigned zbase  = su32(&sm[OFF_Z]);
    const unsigned w1base = su32(&sm[OFF_W1]);
    const unsigned w2base = su32(&sm[OFF_W2]);
    const unsigned b1base = su32(&sm[OFF_B1]);
    const unsigned b2base = su32(&sm[OFF_B2]);

    // ---- aggregation: 4 threads per node, each owns 16 cols (4 float4) ----
    {
        const int l = tid >> 2;        // local node 0..63
        const int q = tid & 3;         // quarter
        const int n = blockIdx.x * NPB + l;
        float4 a0 = {0,0,0,0}, a1 = {0,0,0,0}, a2 = {0,0,0,0}, a3 = {0,0,0,0};
        if (n < N_NODES) {
            const float4* row = (const float4*)hin + n * 16 + q * 4;
            a0 = row[0]; a1 = row[1]; a2 = row[2]; a3 = row[3];
            int beg = __ldg(&g_rowptr[n]);
            int end = __ldg(&g_rowptr[n + 1]);
            for (int e = beg; e < end; e++) {
                int s = __ldg(&g_csr_src[e]);
                const float4* sr = (const float4*)hin + s * 16 + q * 4;
                float4 v0 = sr[0], v1 = sr[1], v2 = sr[2], v3 = sr[3];
                a0.x += v0.x; a0.y += v0.y; a0.z += v0.z; a0.w += v0.w;
                a1.x += v1.x; a1.y += v1.y; a1.z += v1.z; a1.w += v1.w;
                a2.x += v2.x; a2.y += v2.y; a2.z += v2.z; a2.w += v2.w;
                a3.x += v3.x; a3.y += v3.y; a3.z += v3.z; a3.w += v3.w;
            }
        }
        // store transposed + duplicated: z2[k][2l] = z2[k][2l+1] = z
        float v[16] = {a0.x,a0.y,a0.z,a0.w, a1.x,a1.y,a1.z,a1.w,
                       a2.x,a2.y,a2.z,a2.w, a3.x,a3.y,a3.z,a3.w};
        unsigned base = zbase + ((q * 16) * ZPAD + 2 * l) * 4;
#pragma unroll
        for (int m = 0; m < 16; m++)
            asm volatile("st.shared.v2.b32 [%0], {%1, %1};"
                         :: "r"(base + m * (ZPAD * 4)), "f"(v[m]));
    }
    __syncthreads();

    const int jg = tid & 15;           // col group: cols j0..j0+3
    const int ig = tid >> 4;           // node group: nodes i0..i0+3
    const int j0 = jg * 4;
    const int i0 = ig * 4;

    unsigned long long acc[4][2];

    // ================= GEMV 1: y = relu(z @ W1 + b1) =================
    {
        unsigned long long bp0, bp1;
        asm volatile("ld.shared.v2.u64 {%0, %1}, [%2];"
                     : "=l"(bp0), "=l"(bp1) : "r"(b1base + j0 * 4));
#pragma unroll
        for (int a = 0; a < 4; a++) { acc[a][0] = bp0; acc[a][1] = bp1; }

        unsigned waddr = w1base + j0 * 4;
        unsigned zaddr = zbase + 2 * i0 * 4;
#pragma unroll 8
        for (int k = 0; k < HID; k++) {
            unsigned long long w0, w1v, za0, za1, za2, za3;
            asm volatile("ld.shared.v2.u64 {%0, %1}, [%2];"
                         : "=l"(w0), "=l"(w1v) : "r"(waddr));
            asm volatile("ld.shared.v2.u64 {%0, %1}, [%2];"
                         : "=l"(za0), "=l"(za1) : "r"(zaddr));
            asm volatile("ld.shared.v2.u64 {%0, %1}, [%2];"
                         : "=l"(za2), "=l"(za3) : "r"(zaddr + 16));
            FMA2(acc[0][0], za0, w0); FMA2(acc[0][1], za0, w1v);
            FMA2(acc[1][0], za1, w0); FMA2(acc[1][1], za1, w1v);
            FMA2(acc[2][0], za2, w0); FMA2(acc[2][1], za2, w1v);
            FMA2(acc[3][0], za3, w0); FMA2(acc[3][1], za3, w1v);
            waddr += WPAD * 4;
            zaddr += ZPAD * 4;
        }
    }
    __syncthreads();  // all reads of z2 done before overwriting with y

    // relu + write y (transposed, duplicated) back into z2 buffer
    {
#pragma unroll
        for (int a = 0; a < 4; a++) {
            float y0, y1, y2, y3;
            asm("mov.b64 {%0, %1}, %2;" : "=f"(y0), "=f"(y1) : "l"(acc[a][0]));
            asm("mov.b64 {%0, %1}, %2;" : "=f"(y2), "=f"(y3) : "l"(acc[a][1]));
            y0 = fmaxf(y0, 0.f); y1 = fmaxf(y1, 0.f);
            y2 = fmaxf(y2, 0.f); y3 = fmaxf(y3, 0.f);
            unsigned base = zbase + (j0 * ZPAD + 2 * (i0 + a)) * 4;
            asm volatile("st.shared.v2.b32 [%0], {%1, %1};" :: "r"(base + 0 * ZPAD * 4), "f"(y0));
            asm volatile("st.shared.v2.b32 [%0], {%1, %1};" :: "r"(base + 1 * ZPAD * 4), "f"(y1));
            asm volatile("st.shared.v2.b32 [%0], {%1, %1};" :: "r"(base + 2 * ZPAD * 4), "f"(y2));
            asm volatile("st.shared.v2.b32 [%0], {%1, %1};" :: "r"(base + 3 * ZPAD * 4), "f"(y3));
        }
    }
    __syncthreads();

    // ================= GEMV 2: hout = y @ W2 + b2 =================
    {
        unsigned long long bp0, bp1;
        asm volatile("ld.shared.v2.u64 {%0, %1}, [%2];"
                     : "=l"(bp0), "=l"(bp1) : "r"(b2base + j0 * 4));
#pragma unroll
        for (int a = 0; a < 4; a++) { acc[a][0] = bp0; acc[a][1] = bp1; }

        unsigned waddr = w2base + j0 * 4;
        unsigned zaddr = zbase + 2 * i0 * 4;
#pragma unroll 8
        for (int k = 0; k < HID; k++) {
            unsigned long long w0, w1v, za0, za1, za2, za3;
            asm volatile("ld.shared.v2.u64 {%0, %1}, [%2];"
                         : "=l"(w0), "=l"(w1v) : "r"(waddr));
            asm volatile("ld.shared.v2.u64 {%0, %1}, [%2];"
                         : "=l"(za0), "=l"(za1) : "r"(zaddr));
            asm volatile("ld.shared.v2.u64 {%0, %1}, [%2];"
                         : "=l"(za2), "=l"(za3) : "r"(zaddr + 16));
            FMA2(acc[0][0], za0, w0); FMA2(acc[0][1], za0, w1v);
            FMA2(acc[1][0], za1, w0); FMA2(acc[1][1], za1, w1v);
            FMA2(acc[2][0], za2, w0); FMA2(acc[2][1], za2, w1v);
            FMA2(acc[3][0], za3, w0); FMA2(acc[3][1], za3, w1v);
            waddr += WPAD * 4;
            zaddr += ZPAD * 4;
        }

        int nbase = blockIdx.x * NPB + i0;
#pragma unroll
        for (int a = 0; a < 4; a++) {
            int n = nbase + a;
            if (n < N_NODES) {
                float* p = hout + n * HID + j0;
                asm volatile("st.global.v2.u64 [%0], {%1, %2};"
                             :: "l"(p), "l"(acc[a][0]), "l"(acc[a][1]));
            }
        }
    }
}

// ---------------------------------------------------------------------------
// out[g] = sum_{n in g} dot(h[n], Wr)
// ---------------------------------------------------------------------------
__global__ void zero_out_kernel(float* out) {
    if (threadIdx.x < N_GRAPHS) out[threadIdx.x] = 0.f;
}

__global__ void pool_kernel(const int* __restrict__ gids,
                            const float* __restrict__ Wr,
                            float* __restrict__ out) {
    __shared__ float sWr[HID];
    if (threadIdx.x < HID) sWr[threadIdx.x] = Wr[threadIdx.x];
    __syncthreads();
    int n = blockIdx.x * blockDim.x + threadIdx.x;
    bool valid = (n < N_NODES);
    int nn = valid ? n : (N_NODES - 1);
    int g = __ldg(gids + nn);

    float acc = 0.f;
    if (valid) {
        const float4* hrow = ((const float4*)g_h_b) + n * (HID / 4);
#pragma unroll
        for (int c = 0; c < HID / 4; c++) {
            float4 v = hrow[c];
            acc += v.x * sWr[4 * c + 0] + v.y * sWr[4 * c + 1]
                 + v.z * sWr[4 * c + 2] + v.w * sWr[4 * c + 3];
        }
    }
    int g0 = __shfl_sync(0xffffffffu, g, 0);
    bool uniform = __all_sync(0xffffffffu, g == g0);
    if (uniform) {
#pragma unroll
        for (int off = 16; off > 0; off >>= 1)
            acc += __shfl_down_sync(0xffffffffu, acc, off);
        if ((threadIdx.x & 31) == 0) atomicAdd(out + g0, acc);
    } else if (valid) {
        atomicAdd(out + g, acc);
    }
}

// ---------------------------------------------------------------------------
extern "C" void kernel_launch(void* const* d_in, const int* in_sizes, int n_in,
                              void* d_out, int out_size) {
    const int*   feats = (const int*)d_in[0];
    const int*   src   = (const int*)d_in[1];
    const int*   dst   = (const int*)d_in[2];
    const int*   gids  = (const int*)d_in[3];
    const float* emb   = (const float*)d_in[4];
    const float* W1    = (const float*)d_in[5];
    const float* b1    = (const float*)d_in[6];
    const float* W2    = (const float*)d_in[7];
    const float* b2    = (const float*)d_in[8];
    const float* Wr    = (const float*)d_in[9];
    float* out = (float*)d_out;

    cudaFuncSetAttribute(layer_kernel,
                         cudaFuncAttributeMaxDynamicSharedMemorySize, SMEM_BYTES);

    zero_deg_kernel<<<(N_NODES + 255) / 256, 256>>>();
    hist_kernel<<<(N_EDGES + 255) / 256, 256>>>(dst);
    scan_kernel<<<1, 1024>>>();
    scatter_kernel<<<(N_EDGES + 255) / 256, 256>>>(src, dst);

    embed_kernel<<<(N_NODES * 16 + 255) / 256, 256>>>(feats, emb);

    const int nblk = (N_NODES + NPB - 1) / NPB;
    for (int l = 0; l < LAYERS; l++)
        layer_kernel<<<nblk, 256, SMEM_BYTES>>>(W1, b1, W2, b2, l);

    zero_out_kernel<<<1, 128>>>(out);
    pool_kernel<<<(N_NODES + 255) / 256, 256>>>(gids, Wr, out);
}

// round 4
// speedup vs baseline: 1.4116x; 1.1583x over previous
#include <cuda_runtime.h>

#define N_NODES  50000
#define N_EDGES  800000
#define N_GRAPHS 128
#define HID      64
#define LAYERS   3
#define NPB      64   // nodes per block in mlp kernel

// Scratch (__device__ globals — allocation-free rule).
__device__ float g_h_a[N_NODES * HID];
__device__ float g_h_b[N_NODES * HID];
__device__ float g_z[N_NODES * HID];
__device__ int   g_deg[N_NODES];
__device__ int   g_rowptr[N_NODES + 1];
__device__ int   g_pos[N_NODES];
__device__ int   g_csr_src[N_EDGES];

// ---------------------------------------------------------------------------
// CSR build (rebuilt every call: deterministic, graph-capturable)
// ---------------------------------------------------------------------------
__global__ void hist_kernel(const int* __restrict__ dst) {
    int i = blockIdx.x * blockDim.x + threadIdx.x;
    if (i * 4 >= N_EDGES) return;
    int4 d = ((const int4*)dst)[i];
    atomicAdd(&g_deg[d.x], 1);
    atomicAdd(&g_deg[d.y], 1);
    atomicAdd(&g_deg[d.z], 1);
    atomicAdd(&g_deg[d.w], 1);
}

__global__ void __launch_bounds__(1024) scan_kernel() {
    __shared__ int ssum[1024];
    const int CH = (N_NODES + 1023) / 1024;  // 49
    int t = threadIdx.x;
    int beg = t * CH;
    int end = beg + CH; if (end > N_NODES) end = N_NODES;
    int s = 0;
    for (int i = beg; i < end; i++) s += g_deg[i];
    ssum[t] = s;
    __syncthreads();
    for (int off = 1; off < 1024; off <<= 1) {
        int v = (t >= off) ? ssum[t - off] : 0;
        __syncthreads();
        ssum[t] += v;
        __syncthreads();
    }
    int run = ssum[t] - s;
    for (int i = beg; i < end; i++) {
        g_rowptr[i] = run;
        g_pos[i]    = run;
        run += g_deg[i];
    }
    if (t == 0) g_rowptr[N_NODES] = N_EDGES;
}

__global__ void scatter_kernel(const int* __restrict__ src,
                               const int* __restrict__ dst) {
    int e = blockIdx.x * blockDim.x + threadIdx.x;
    if (e >= N_EDGES) return;
    int p = atomicAdd(&g_pos[__ldg(dst + e)], 1);
    g_csr_src[p] = __ldg(src + e);
}

// ---------------------------------------------------------------------------
// h[n] = emb[feats[n]]
// ---------------------------------------------------------------------------
__global__ void embed_kernel(const int* __restrict__ feats,
                             const float* __restrict__ emb) {
    int i = blockIdx.x * blockDim.x + threadIdx.x;
    if (i >= N_NODES * (HID / 4)) return;
    int n = i >> 4;
    int c = i & 15;
    int f = __ldg(feats + n);
    ((float4*)g_h_a)[i] = ((const float4*)emb)[f * (HID / 4) + c];
}

// ---------------------------------------------------------------------------
// Aggregation: z[n] = h[n] + sum_{s in N(n)} h[s]
// 16 threads per node (one float4 column each). Edge loop batched x8:
// 8 independent index loads, then 8 independent float4 row loads -> high MLP.
// No smem -> full occupancy; gather is L2-bandwidth-bound, not latency-bound.
// ---------------------------------------------------------------------------
__global__ void __launch_bounds__(256)
agg_kernel(int layer) {
    const float* hin = (layer & 1) ? g_h_b : g_h_a;
    int i = blockIdx.x * blockDim.x + threadIdx.x;
    if (i >= N_NODES * 16) return;
    int n = i >> 4;
    int c = i & 15;
    const float4* h4 = (const float4*)hin;

    float4 acc = h4[n * 16 + c];
    int e   = __ldg(&g_rowptr[n]);
    int end = __ldg(&g_rowptr[n + 1]);

    for (; e + 8 <= end; e += 8) {
        int s0 = __ldg(&g_csr_src[e + 0]);
        int s1 = __ldg(&g_csr_src[e + 1]);
        int s2 = __ldg(&g_csr_src[e + 2]);
        int s3 = __ldg(&g_csr_src[e + 3]);
        int s4 = __ldg(&g_csr_src[e + 4]);
        int s5 = __ldg(&g_csr_src[e + 5]);
        int s6 = __ldg(&g_csr_src[e + 6]);
        int s7 = __ldg(&g_csr_src[e + 7]);
        float4 v0 = h4[s0 * 16 + c];
        float4 v1 = h4[s1 * 16 + c];
        float4 v2 = h4[s2 * 16 + c];
        float4 v3 = h4[s3 * 16 + c];
        float4 v4 = h4[s4 * 16 + c];
        float4 v5 = h4[s5 * 16 + c];
        float4 v6 = h4[s6 * 16 + c];
        float4 v7 = h4[s7 * 16 + c];
        acc.x += v0.x; acc.y += v0.y; acc.z += v0.z; acc.w += v0.w;
        acc.x += v1.x; acc.y += v1.y; acc.z += v1.z; acc.w += v1.w;
        acc.x += v2.x; acc.y += v2.y; acc.z += v2.z; acc.w += v2.w;
        acc.x += v3.x; acc.y += v3.y; acc.z += v3.z; acc.w += v3.w;
        acc.x += v4.x; acc.y += v4.y; acc.z += v4.z; acc.w += v4.w;
        acc.x += v5.x; acc.y += v5.y; acc.z += v5.z; acc.w += v5.w;
        acc.x += v6.x; acc.y += v6.y; acc.z += v6.z; acc.w += v6.w;
        acc.x += v7.x; acc.y += v7.y; acc.z += v7.z; acc.w += v7.w;
    }
    for (; e < end; e++) {
        int s = __ldg(&g_csr_src[e]);
        float4 v = h4[s * 16 + c];
        acc.x += v.x; acc.y += v.y; acc.z += v.z; acc.w += v.w;
    }
    ((float4*)g_z)[n * 16 + c] = acc;
}

// ---------------------------------------------------------------------------
// MLP: hout = relu(z@W1+b1)@W2 + b2
// Shared layout (floats, dynamic smem):
//   sW1 : [64][68]       off 0
//   sW2 : [64][68]       off 4352
//   sb1 : [64]           off 8704
//   sb2 : [64]           off 8768
//   z2  : [64][132]      off 8832  (transposed, DUPLICATED: z2[k][2n]=z2[k][2n+1])
// 256 threads: jg=tid&15 (4 output cols), ig=tid>>4 (4 nodes).
// Inner loop: 3x LDS.128 + 8x fma.rn.f32x2 per k (16 FMAs/thread/k).
// ---------------------------------------------------------------------------
#define OFF_W1 0
#define OFF_W2 4352
#define OFF_B1 8704
#define OFF_B2 8768
#define OFF_Z  8832
#define WPAD   68
#define ZPAD   132
#define SMEM_BYTES (17280 * 4)

__device__ __forceinline__ unsigned su32(const void* p) {
    return (unsigned)__cvta_generic_to_shared(p);
}

#define FMA2(d, a, b) asm("fma.rn.f32x2 %0, %1, %2, %0;" : "+l"(d) : "l"(a), "l"(b))

__global__ void __launch_bounds__(256)
mlp_kernel(const float* __restrict__ W1, const float* __restrict__ b1,
           const float* __restrict__ W2, const float* __restrict__ b2,
           int layer) {
    extern __shared__ __align__(16) float sm[];

    float* hout = (layer & 1) ? g_h_a : g_h_b;
    const int tid = threadIdx.x;

    // ---- stage weights/biases (padded rows) ----
    {
        const float4* w1 = (const float4*)(W1 + layer * HID * HID);
        const float4* w2 = (const float4*)(W2 + layer * HID * HID);
        for (int idx = tid; idx < 1024; idx += 256) {
            int r = idx >> 4, c = idx & 15;
            *(float4*)&sm[OFF_W1 + r * WPAD + c * 4] = w1[idx];
            *(float4*)&sm[OFF_W2 + r * WPAD + c * 4] = w2[idx];
        }
        if (tid < HID) {
            sm[OFF_B1 + tid] = b1[layer * HID + tid];
            sm[OFF_B2 + tid] = b2[layer * HID + tid];
        }
    }

    const unsigned zbase  = su32(&sm[OFF_Z]);
    const unsigned w1base = su32(&sm[OFF_W1]);
    const unsigned w2base = su32(&sm[OFF_W2]);
    const unsigned b1base = su32(&sm[OFF_B1]);
    const unsigned b2base = su32(&sm[OFF_B2]);

    // ---- stage z tile: 4 threads per node, transposed + duplicated ----
    {
        const int l = tid >> 2;        // local node 0..63
        const int q = tid & 3;         // quarter
        const int n = blockIdx.x * NPB + l;
        float4 a0 = {0,0,0,0}, a1 = {0,0,0,0}, a2 = {0,0,0,0}, a3 = {0,0,0,0};
        if (n < N_NODES) {
            const float4* row = (const float4*)g_z + n * 16 + q * 4;
            a0 = row[0]; a1 = row[1]; a2 = row[2]; a3 = row[3];
        }
        float v[16] = {a0.x,a0.y,a0.z,a0.w, a1.x,a1.y,a1.z,a1.w,
                       a2.x,a2.y,a2.z,a2.w, a3.x,a3.y,a3.z,a3.w};
        unsigned base = zbase + ((q * 16) * ZPAD + 2 * l) * 4;
#pragma unroll
        for (int m = 0; m < 16; m++)
            asm volatile("st.shared.v2.b32 [%0], {%1, %1};"
                         :: "r"(base + m * (ZPAD * 4)), "f"(v[m]));
    }
    __syncthreads();

    const int jg = tid & 15;
    const int ig = tid >> 4;
    const int j0 = jg * 4;
    const int i0 = ig * 4;

    unsigned long long acc[4][2];

    // ================= GEMV 1: y = relu(z @ W1 + b1) =================
    {
        unsigned long long bp0, bp1;
        asm volatile("ld.shared.v2.u64 {%0, %1}, [%2];"
                     : "=l"(bp0), "=l"(bp1) : "r"(b1base + j0 * 4));
#pragma unroll
        for (int a = 0; a < 4; a++) { acc[a][0] = bp0; acc[a][1] = bp1; }

        unsigned waddr = w1base + j0 * 4;
        unsigned zaddr = zbase + 2 * i0 * 4;
#pragma unroll 8
        for (int k = 0; k < HID; k++) {
            unsigned long long w0, w1v, za0, za1, za2, za3;
            asm volatile("ld.shared.v2.u64 {%0, %1}, [%2];"
                         : "=l"(w0), "=l"(w1v) : "r"(waddr));
            asm volatile("ld.shared.v2.u64 {%0, %1}, [%2];"
                         : "=l"(za0), "=l"(za1) : "r"(zaddr));
            asm volatile("ld.shared.v2.u64 {%0, %1}, [%2];"
                         : "=l"(za2), "=l"(za3) : "r"(zaddr + 16));
            FMA2(acc[0][0], za0, w0); FMA2(acc[0][1], za0, w1v);
            FMA2(acc[1][0], za1, w0); FMA2(acc[1][1], za1, w1v);
            FMA2(acc[2][0], za2, w0); FMA2(acc[2][1], za2, w1v);
            FMA2(acc[3][0], za3, w0); FMA2(acc[3][1], za3, w1v);
            waddr += WPAD * 4;
            zaddr += ZPAD * 4;
        }
    }
    __syncthreads();

    // relu + write y (transposed, duplicated) back into z2 buffer
    {
#pragma unroll
        for (int a = 0; a < 4; a++) {
            float y0, y1, y2, y3;
            asm("mov.b64 {%0, %1}, %2;" : "=f"(y0), "=f"(y1) : "l"(acc[a][0]));
            asm("mov.b64 {%0, %1}, %2;" : "=f"(y2), "=f"(y3) : "l"(acc[a][1]));
            y0 = fmaxf(y0, 0.f); y1 = fmaxf(y1, 0.f);
            y2 = fmaxf(y2, 0.f); y3 = fmaxf(y3, 0.f);
            unsigned base = zbase + (j0 * ZPAD + 2 * (i0 + a)) * 4;
            asm volatile("st.shared.v2.b32 [%0], {%1, %1};" :: "r"(base + 0 * ZPAD * 4), "f"(y0));
            asm volatile("st.shared.v2.b32 [%0], {%1, %1};" :: "r"(base + 1 * ZPAD * 4), "f"(y1));
            asm volatile("st.shared.v2.b32 [%0], {%1, %1};" :: "r"(base + 2 * ZPAD * 4), "f"(y2));
            asm volatile("st.shared.v2.b32 [%0], {%1, %1};" :: "r"(base + 3 * ZPAD * 4), "f"(y3));
        }
    }
    __syncthreads();

    // ================= GEMV 2: hout = y @ W2 + b2 =================
    {
        unsigned long long bp0, bp1;
        asm volatile("ld.shared.v2.u64 {%0, %1}, [%2];"
                     : "=l"(bp0), "=l"(bp1) : "r"(b2base + j0 * 4));
#pragma unroll
        for (int a = 0; a < 4; a++) { acc[a][0] = bp0; acc[a][1] = bp1; }

        unsigned waddr = w2base + j0 * 4;
        unsigned zaddr = zbase + 2 * i0 * 4;
#pragma unroll 8
        for (int k = 0; k < HID; k++) {
            unsigned long long w0, w1v, za0, za1, za2, za3;
            asm volatile("ld.shared.v2.u64 {%0, %1}, [%2];"
                         : "=l"(w0), "=l"(w1v) : "r"(waddr));
            asm volatile("ld.shared.v2.u64 {%0, %1}, [%2];"
                         : "=l"(za0), "=l"(za1) : "r"(zaddr));
            asm volatile("ld.shared.v2.u64 {%0, %1}, [%2];"
                         : "=l"(za2), "=l"(za3) : "r"(zaddr + 16));
            FMA2(acc[0][0], za0, w0); FMA2(acc[0][1], za0, w1v);
            FMA2(acc[1][0], za1, w0); FMA2(acc[1][1], za1, w1v);
            FMA2(acc[2][0], za2, w0); FMA2(acc[2][1], za2, w1v);
            FMA2(acc[3][0], za3, w0); FMA2(acc[3][1], za3, w1v);
            waddr += WPAD * 4;
            zaddr += ZPAD * 4;
        }

        int nbase = blockIdx.x * NPB + i0;
#pragma unroll
        for (int a = 0; a < 4; a++) {
            int n = nbase + a;
            if (n < N_NODES) {
                float* p = hout + n * HID + j0;
                asm volatile("st.global.v2.u64 [%0], {%1, %2};"
                             :: "l"(p), "l"(acc[a][0]), "l"(acc[a][1]));
            }
        }
    }
}

// ---------------------------------------------------------------------------
// out[g] = sum_{n in g} dot(h[n], Wr)
// ---------------------------------------------------------------------------
__global__ void pool_kernel(const int* __restrict__ gids,
                            const float* __restrict__ Wr,
                            float* __restrict__ out) {
    __shared__ float sWr[HID];
    if (threadIdx.x < HID) sWr[threadIdx.x] = Wr[threadIdx.x];
    __syncthreads();
    int n = blockIdx.x * blockDim.x + threadIdx.x;
    bool valid = (n < N_NODES);
    int nn = valid ? n : (N_NODES - 1);
    int g = __ldg(gids + nn);

    float acc = 0.f;
    if (valid) {
        const float4* hrow = ((const float4*)g_h_b) + n * (HID / 4);
#pragma unroll
        for (int c = 0; c < HID / 4; c++) {
            float4 v = hrow[c];
            acc += v.x * sWr[4 * c + 0] + v.y * sWr[4 * c + 1]
                 + v.z * sWr[4 * c + 2] + v.w * sWr[4 * c + 3];
        }
    }
    int g0 = __shfl_sync(0xffffffffu, g, 0);
    bool uniform = __all_sync(0xffffffffu, g == g0);
    if (uniform) {
#pragma unroll
        for (int off = 16; off > 0; off >>= 1)
            acc += __shfl_down_sync(0xffffffffu, acc, off);
        if ((threadIdx.x & 31) == 0) atomicAdd(out + g0, acc);
    } else if (valid) {
        atomicAdd(out + g, acc);
    }
}

// ---------------------------------------------------------------------------
extern "C" void kernel_launch(void* const* d_in, const int* in_sizes, int n_in,
                              void* d_out, int out_size) {
    const int*   feats = (const int*)d_in[0];
    const int*   src   = (const int*)d_in[1];
    const int*   dst   = (const int*)d_in[2];
    const int*   gids  = (const int*)d_in[3];
    const float* emb   = (const float*)d_in[4];
    const float* W1    = (const float*)d_in[5];
    const float* b1    = (const float*)d_in[6];
    const float* W2    = (const float*)d_in[7];
    const float* b2    = (const float*)d_in[8];
    const float* Wr    = (const float*)d_in[9];
    float* out = (float*)d_out;

    cudaFuncSetAttribute(mlp_kernel,
                         cudaFuncAttributeMaxDynamicSharedMemorySize, SMEM_BYTES);

    // CSR build
    void* deg_ptr = nullptr;
    cudaGetSymbolAddress(&deg_ptr, g_deg);
    cudaMemsetAsync(deg_ptr, 0, N_NODES * sizeof(int));
    hist_kernel<<<(N_EDGES / 4 + 255) / 256, 256>>>(dst);
    scan_kernel<<<1, 1024>>>();
    scatter_kernel<<<(N_EDGES + 255) / 256, 256>>>(src, dst);

    // Embedding
    embed_kernel<<<(N_NODES * 16 + 255) / 256, 256>>>(feats, emb);

    // 3 GIN layers: agg (gather) -> mlp
    const int ablk = (N_NODES * 16 + 255) / 256;
    const int mblk = (N_NODES + NPB - 1) / NPB;
    for (int l = 0; l < LAYERS; l++) {
        agg_kernel<<<ablk, 256>>>(l);
        mlp_kernel<<<mblk, 256, SMEM_BYTES>>>(W1, b1, W2, b2, l);
    }

    // Pool + head
    cudaMemsetAsync(out, 0, N_GRAPHS * sizeof(float));
    pool_kernel<<<(N_NODES + 255) / 256, 256>>>(gids, Wr, out);
}

// round 5
// speedup vs baseline: 1.5673x; 1.1103x over previous
#include <cuda_runtime.h>

#define N_NODES  50000
#define N_EDGES  800000
#define N_GRAPHS 128
#define HID      64
#define LAYERS   3
#define NPB      128                          // nodes per block in mlp kernel
#define CSR_CAP  (N_EDGES + 7 * N_NODES)      // padded CSR capacity

// Scratch (__device__ globals — allocation-free rule).
// Row N_NODES of g_h_a/g_h_b is a permanent ZERO row (zero-initialized at
// module load, never written) used as the padded-CSR dummy gather target.
__device__ float g_h_a[(N_NODES + 1) * HID];
__device__ float g_h_b[(N_NODES + 1) * HID];
__device__ float g_z[N_NODES * HID];
__device__ int   g_deg[N_NODES];
__device__ int   g_rowptr[N_NODES + 1];
__device__ int   g_pos[N_NODES];
__device__ int   g_csr_src[CSR_CAP];

// ---------------------------------------------------------------------------
// CSR build (rebuilt every call: deterministic, graph-capturable)
// ---------------------------------------------------------------------------
__global__ void hist_kernel(const int* __restrict__ dst) {
    int i = blockIdx.x * blockDim.x + threadIdx.x;
    if (i * 4 >= N_EDGES) return;
    int4 d = ((const int4*)dst)[i];
    atomicAdd(&g_deg[d.x], 1);
    atomicAdd(&g_deg[d.y], 1);
    atomicAdd(&g_deg[d.z], 1);
    atomicAdd(&g_deg[d.w], 1);
}

__global__ void fill_kernel() {
    int i = blockIdx.x * blockDim.x + threadIdx.x;
    if (i * 4 < CSR_CAP)
        ((int4*)g_csr_src)[i] = make_int4(N_NODES, N_NODES, N_NODES, N_NODES);
}

// Scan PADDED degrees (rounded up to multiple of 8) -> rowptr; g_pos = rowptr.
__global__ void __launch_bounds__(1024) scan_kernel() {
    __shared__ int ssum[1024];
    const int CH = (N_NODES + 1023) / 1024;  // 49
    int t = threadIdx.x;
    int beg = t * CH;
    int end = beg + CH; if (end > N_NODES) end = N_NODES;
    int s = 0;
    for (int i = beg; i < end; i++) s += (g_deg[i] + 7) & ~7;
    ssum[t] = s;
    __syncthreads();
    for (int off = 1; off < 1024; off <<= 1) {
        int v = (t >= off) ? ssum[t - off] : 0;
        __syncthreads();
        ssum[t] += v;
        __syncthreads();
    }
    int run = ssum[t] - s;
    for (int i = beg; i < end; i++) {
        g_rowptr[i] = run;
        g_pos[i]    = run;
        run += (g_deg[i] + 7) & ~7;
    }
    if (t == 1023) g_rowptr[N_NODES] = ssum[1023];
}

__global__ void scatter_kernel(const int* __restrict__ src,
                               const int* __restrict__ dst) {
    int e = blockIdx.x * blockDim.x + threadIdx.x;
    if (e >= N_EDGES) return;
    int p = atomicAdd(&g_pos[__ldg(dst + e)], 1);
    g_csr_src[p] = __ldg(src + e);
}

// ---------------------------------------------------------------------------
// h[n] = emb[feats[n]]
// ---------------------------------------------------------------------------
__global__ void embed_kernel(const int* __restrict__ feats,
                             const float* __restrict__ emb) {
    int i = blockIdx.x * blockDim.x + threadIdx.x;
    if (i >= N_NODES * (HID / 4)) return;
    int n = i >> 4;
    int c = i & 15;
    int f = __ldg(feats + n);
    ((float4*)g_h_a)[i] = ((const float4*)emb)[f * (HID / 4) + c];
}

// ---------------------------------------------------------------------------
// Aggregation: z[n] = h[n] + sum_{s in N(n)} h[s]
// 16 threads per node (one float4 column each). CSR rows are padded to
// multiples of 8 with dummy index N_NODES (zero row) -> NO remainder loop,
// every iteration is an 8-deep independent-load batch (high MLP, no serial
// latency tail).
// ---------------------------------------------------------------------------
__global__ void __launch_bounds__(256)
agg_kernel(int layer) {
    const float* hin = (layer & 1) ? g_h_b : g_h_a;
    int i = blockIdx.x * blockDim.x + threadIdx.x;
    if (i >= N_NODES * 16) return;
    int n = i >> 4;
    int c = i & 15;
    const float4* h4 = (const float4*)hin;

    float4 acc = h4[n * 16 + c];
    int e   = __ldg(&g_rowptr[n]);
    int end = __ldg(&g_rowptr[n + 1]);

    for (; e < end; e += 8) {
        int s0 = __ldg(&g_csr_src[e + 0]);
        int s1 = __ldg(&g_csr_src[e + 1]);
        int s2 = __ldg(&g_csr_src[e + 2]);
        int s3 = __ldg(&g_csr_src[e + 3]);
        int s4 = __ldg(&g_csr_src[e + 4]);
        int s5 = __ldg(&g_csr_src[e + 5]);
        int s6 = __ldg(&g_csr_src[e + 6]);
        int s7 = __ldg(&g_csr_src[e + 7]);
        float4 v0 = h4[s0 * 16 + c];
        float4 v1 = h4[s1 * 16 + c];
        float4 v2 = h4[s2 * 16 + c];
        float4 v3 = h4[s3 * 16 + c];
        float4 v4 = h4[s4 * 16 + c];
        float4 v5 = h4[s5 * 16 + c];
        float4 v6 = h4[s6 * 16 + c];
        float4 v7 = h4[s7 * 16 + c];
        acc.x += v0.x; acc.y += v0.y; acc.z += v0.z; acc.w += v0.w;
        acc.x += v1.x; acc.y += v1.y; acc.z += v1.z; acc.w += v1.w;
        acc.x += v2.x; acc.y += v2.y; acc.z += v2.z; acc.w += v2.w;
        acc.x += v3.x; acc.y += v3.y; acc.z += v3.z; acc.w += v3.w;
        acc.x += v4.x; acc.y += v4.y; acc.z += v4.z; acc.w += v4.w;
        acc.x += v5.x; acc.y += v5.y; acc.z += v5.z; acc.w += v5.w;
        acc.x += v6.x; acc.y += v6.y; acc.z += v6.z; acc.w += v6.w;
        acc.x += v7.x; acc.y += v7.y; acc.z += v7.z; acc.w += v7.w;
    }
    ((float4*)g_z)[n * 16 + c] = acc;
}

// ---------------------------------------------------------------------------
// MLP: hout = relu(z@W1+b1)@W2 + b2
// 128 threads, 128 nodes/block. Thread = 8 nodes x 8 cols (node-paired fma2).
// Shared (floats): W1[64][68] @0, W2[64][68] @4352, b1 @8704, b2 @8768,
//                  z/y transposed non-dup [64][132] @8832. Total 69120 B.
// Per k: 2x LDS.v2.u64 (z pairs) + 8 scalar LDS (w, warp-dedup'd) +
//        8 in-reg dups + 32 fma2 (64 FMADD).
// ---------------------------------------------------------------------------
#define OFF_W1 0
#define OFF_W2 4352
#define OFF_B1 8704
#define OFF_B2 8768
#define OFF_Z  8832
#define WPAD   68
#define ZPAD   132
#define SMEM_BYTES (17280 * 4)

__device__ __forceinline__ unsigned su32(const void* p) {
    return (unsigned)__cvta_generic_to_shared(p);
}
__device__ __forceinline__ unsigned long long dupf(float x) {
    unsigned long long r;
    asm("mov.b64 %0, {%1, %1};" : "=l"(r) : "f"(x));
    return r;
}
#define FMA2(d, a, b) asm("fma.rn.f32x2 %0, %1, %2, %0;" : "+l"(d) : "l"(a), "l"(b))

__global__ void __launch_bounds__(128)
mlp_kernel(const float* __restrict__ W1, const float* __restrict__ b1,
           const float* __restrict__ W2, const float* __restrict__ b2,
           int layer) {
    extern __shared__ __align__(16) float sm[];
    float* hout = (layer & 1) ? g_h_a : g_h_b;
    const int tid = threadIdx.x;
    const int nbase = blockIdx.x * NPB;

    // ---- stage weights/biases ----
    {
        const float4* w1 = (const float4*)(W1 + layer * HID * HID);
        const float4* w2 = (const float4*)(W2 + layer * HID * HID);
        for (int idx = tid; idx < 1024; idx += 128) {
            int r = idx >> 4, c = idx & 15;
            *(float4*)&sm[OFF_W1 + r * WPAD + c * 4] = w1[idx];
            *(float4*)&sm[OFF_W2 + r * WPAD + c * 4] = w2[idx];
        }
        if (tid < HID) {
            sm[OFF_B1 + tid] = b1[layer * HID + tid];
            sm[OFF_B2 + tid] = b2[layer * HID + tid];
        }
    }

    // ---- stage z transposed (non-duplicated): sz[k][node] ----
    {
        int n = nbase + tid;
        float v[64];
        if (n < N_NODES) {
            const float4* zr = (const float4*)(g_z + n * HID);
#pragma unroll
            for (int q = 0; q < 16; q++) {
                float4 t4 = zr[q];
                v[4 * q + 0] = t4.x; v[4 * q + 1] = t4.y;
                v[4 * q + 2] = t4.z; v[4 * q + 3] = t4.w;
            }
        } else {
#pragma unroll
            for (int q = 0; q < 64; q++) v[q] = 0.f;
        }
#pragma unroll
        for (int k = 0; k < 64; k++) sm[OFF_Z + k * ZPAD + tid] = v[k];
    }
    __syncthreads();

    const int jg = tid & 7;          // col group: cols j0..j0+7
    const int ig = tid >> 3;         // node group: nodes i0..i0+7
    const int j0 = jg * 8;
    const int i0 = ig * 8;
    const unsigned zb = su32(sm + OFF_Z);

    unsigned long long acc[4][8];

    // ================= GEMV 1: y = relu(z @ W1 + b1) =================
    {
#pragma unroll
        for (int j = 0; j < 8; j++) {
            unsigned long long bd = dupf(sm[OFF_B1 + j0 + j]);
            acc[0][j] = bd; acc[1][j] = bd; acc[2][j] = bd; acc[3][j] = bd;
        }
        unsigned za = zb + i0 * 4;
#pragma unroll 4
        for (int k = 0; k < 64; k++) {
            unsigned long long z0, z1, z2, z3;
            asm("ld.shared.v2.u64 {%0,%1},[%2];" : "=l"(z0), "=l"(z1) : "r"(za));
            asm("ld.shared.v2.u64 {%0,%1},[%2];" : "=l"(z2), "=l"(z3) : "r"(za + 16));
#pragma unroll
            for (int j = 0; j < 8; j++) {
                unsigned long long wd = dupf(sm[OFF_W1 + k * WPAD + j0 + j]);
                FMA2(acc[0][j], z0, wd);
                FMA2(acc[1][j], z1, wd);
                FMA2(acc[2][j], z2, wd);
                FMA2(acc[3][j], z3, wd);
            }
            za += ZPAD * 4;
        }
    }
    __syncthreads();  // all z reads done before overwriting with y

    // relu + store y transposed (natural node pairs)
    {
#pragma unroll
        for (int p = 0; p < 4; p++) {
#pragma unroll
            for (int j = 0; j < 8; j++) {
                float lo, hi;
                asm("mov.b64 {%0,%1},%2;" : "=f"(lo), "=f"(hi) : "l"(acc[p][j]));
                lo = fmaxf(lo, 0.f);
                hi = fmaxf(hi, 0.f);
                unsigned ya = zb + (unsigned)((j0 + j) * ZPAD + i0 + 2 * p) * 4;
                asm volatile("st.shared.v2.b32 [%0],{%1,%2};"
                             :: "r"(ya), "f"(lo), "f"(hi));
            }
        }
    }
    __syncthreads();

    // ================= GEMV 2: hout = y @ W2 + b2 =================
    {
#pragma unroll
        for (int j = 0; j < 8; j++) {
            unsigned long long bd = dupf(sm[OFF_B2 + j0 + j]);
            acc[0][j] = bd; acc[1][j] = bd; acc[2][j] = bd; acc[3][j] = bd;
        }
        unsigned za = zb + i0 * 4;
#pragma unroll 4
        for (int k = 0; k < 64; k++) {
            unsigned long long z0, z1, z2, z3;
            asm("ld.shared.v2.u64 {%0,%1},[%2];" : "=l"(z0), "=l"(z1) : "r"(za));
            asm("ld.shared.v2.u64 {%0,%1},[%2];" : "=l"(z2), "=l"(z3) : "r"(za + 16));
#pragma unroll
            for (int j = 0; j < 8; j++) {
                unsigned long long wd = dupf(sm[OFF_W2 + k * WPAD + j0 + j]);
                FMA2(acc[0][j], z0, wd);
                FMA2(acc[1][j], z1, wd);
                FMA2(acc[2][j], z2, wd);
                FMA2(acc[3][j], z3, wd);
            }
            za += ZPAD * 4;
        }

#pragma unroll
        for (int p = 0; p < 4; p++) {
            int n0 = nbase + i0 + 2 * p;
            float lo[8], hi[8];
#pragma unroll
            for (int j = 0; j < 8; j++)
                asm("mov.b64 {%0,%1},%2;" : "=f"(lo[j]), "=f"(hi[j]) : "l"(acc[p][j]));
            if (n0 < N_NODES) {
                float* pn = hout + n0 * HID + j0;
                *(float4*)(pn)     = make_float4(lo[0], lo[1], lo[2], lo[3]);
                *(float4*)(pn + 4) = make_float4(lo[4], lo[5], lo[6], lo[7]);
            }
            if (n0 + 1 < N_NODES) {
                float* pn = hout + (n0 + 1) * HID + j0;
                *(float4*)(pn)     = make_float4(hi[0], hi[1], hi[2], hi[3]);
                *(float4*)(pn + 4) = make_float4(hi[4], hi[5], hi[6], hi[7]);
            }
        }
    }
}

// ---------------------------------------------------------------------------
// out[g] = sum_{n in g} dot(h[n], Wr)
// ---------------------------------------------------------------------------
__global__ void pool_kernel(const int* __restrict__ gids,
                            const float* __restrict__ Wr,
                            float* __restrict__ out) {
    __shared__ float sWr[HID];
    if (threadIdx.x < HID) sWr[threadIdx.x] = Wr[threadIdx.x];
    __syncthreads();
    int n = blockIdx.x * blockDim.x + threadIdx.x;
    bool valid = (n < N_NODES);
    int nn = valid ? n : (N_NODES - 1);
    int g = __ldg(gids + nn);

    float acc = 0.f;
    if (valid) {
        const float4* hrow = ((const float4*)g_h_b) + n * (HID / 4);
#pragma unroll
        for (int c = 0; c < HID / 4; c++) {
            float4 v = hrow[c];
            acc += v.x * sWr[4 * c + 0] + v.y * sWr[4 * c + 1]
                 + v.z * sWr[4 * c + 2] + v.w * sWr[4 * c + 3];
        }
    }
    int g0 = __shfl_sync(0xffffffffu, g, 0);
    bool uniform = __all_sync(0xffffffffu, g == g0);
    if (uniform) {
#pragma unroll
        for (int off = 16; off > 0; off >>= 1)
            acc += __shfl_down_sync(0xffffffffu, acc, off);
        if ((threadIdx.x & 31) == 0) atomicAdd(out + g0, acc);
    } else if (valid) {
        atomicAdd(out + g, acc);
    }
}

// ---------------------------------------------------------------------------
extern "C" void kernel_launch(void* const* d_in, const int* in_sizes, int n_in,
                              void* d_out, int out_size) {
    const int*   feats = (const int*)d_in[0];
    const int*   src   = (const int*)d_in[1];
    const int*   dst   = (const int*)d_in[2];
    const int*   gids  = (const int*)d_in[3];
    const float* emb   = (const float*)d_in[4];
    const float* W1    = (const float*)d_in[5];
    const float* b1    = (const float*)d_in[6];
    const float* W2    = (const float*)d_in[7];
    const float* b2    = (const float*)d_in[8];
    const float* Wr    = (const float*)d_in[9];
    float* out = (float*)d_out;

    cudaFuncSetAttribute(mlp_kernel,
                         cudaFuncAttributeMaxDynamicSharedMemorySize, SMEM_BYTES);

    // CSR build (padded rows)
    void* deg_ptr = nullptr;
    cudaGetSymbolAddress(&deg_ptr, g_deg);
    cudaMemsetAsync(deg_ptr, 0, N_NODES * sizeof(int));
    fill_kernel<<<(CSR_CAP / 4 + 255) / 256, 256>>>();
    hist_kernel<<<(N_EDGES / 4 + 255) / 256, 256>>>(dst);
    scan_kernel<<<1, 1024>>>();
    scatter_kernel<<<(N_EDGES + 255) / 256, 256>>>(src, dst);

    // Embedding
    embed_kernel<<<(N_NODES * 16 + 255) / 256, 256>>>(feats, emb);

    // 3 GIN layers: agg (gather) -> mlp
    const int ablk = (N_NODES * 16 + 255) / 256;
    const int mblk = (N_NODES + NPB - 1) / NPB;
    for (int l = 0; l < LAYERS; l++) {
        agg_kernel<<<ablk, 256>>>(l);
        mlp_kernel<<<mblk, 128, SMEM_BYTES>>>(W1, b1, W2, b2, l);
    }

    // Pool + head
    cudaMemsetAsync(out, 0, N_GRAPHS * sizeof(float));
    pool_kernel<<<(N_NODES + 255) / 256, 256>>>(gids, Wr, out);
}